// round 6
// baseline (speedup 1.0000x reference)
#include <cuda_runtime.h>
#include <cuda_bf16.h>
#include <cstdint>

#define INPUT_DIM 16384
#define EMB 1024
#define BATCH 4096
#define XS_N (INPUT_DIM + EMB * 3)   // 19456 floats, pad-4 bound (<32768, fits 15 bits)

// ---------------- device scratch ----------------
__device__ unsigned short g_comb[INPUT_DIM];                 // e | (neg<<15) per feature j
__device__ __align__(16) unsigned short g_pos[INPUT_DIM];    // slot | (neg<<15), by j
__device__ __align__(16) unsigned short g_sched[EMB];        // bucket ids sorted by length desc
__device__ int g_astart[EMB];                                // pad-4 bucket start
__device__ int g_len[EMB];                                   // actual bucket length

// ---------------- K1: extract (bucket, sign) per feature row, warp-uniform early exit ----------------
__global__ void k_extract(const float* __restrict__ hp) {
    int warp = (blockIdx.x * blockDim.x + threadIdx.x) >> 5;
    int lane = threadIdx.x & 31;
    if (warp >= INPUT_DIM) return;

    const float4* row = reinterpret_cast<const float4*>(hp + (size_t)warp * EMB);
    int my_e = 0; unsigned my_neg = 0;
    unsigned mask = 0;
    for (int i = 0; i < 8; i++) {                  // 8 chunks of 128 cols
        int idx4 = lane + i * 32;
        float4 v = row[idx4];
        int base = idx4 * 4;
        bool has = false;
        if (v.x != 0.0f) { my_e = base + 0; my_neg = (v.x < 0.0f); has = true; }
        if (v.y != 0.0f) { my_e = base + 1; my_neg = (v.y < 0.0f); has = true; }
        if (v.z != 0.0f) { my_e = base + 2; my_neg = (v.z < 0.0f); has = true; }
        if (v.w != 0.0f) { my_e = base + 3; my_neg = (v.w < 0.0f); has = true; }
        mask = __ballot_sync(0xffffffffu, has);
        if (mask) break;                           // uniform exit: expected 4.5/8 chunks read
    }
    if (mask == 0) { if (lane == 0) g_comb[warp] = 0; return; }
    int src = __ffs(mask) - 1;
    int e        = __shfl_sync(0xffffffffu, my_e, src);
    unsigned neg = __shfl_sync(0xffffffffu, my_neg, src);
    if (lane == 0) g_comb[warp] = (unsigned short)(e | (neg << 15));
}

// ---------------- K2: fused build — histogram, shuffle-scan, length-sort, slot assign ----------------
__global__ __launch_bounds__(EMB, 1)
void k_build() {
    __shared__ int hist[EMB];
    __shared__ int cur[EMB];
    __shared__ int wsum[32];
    __shared__ int hc[64];
    __shared__ int hoff[64];
    int t = threadIdx.x;
    int lane = t & 31, w = t >> 5;

    hist[t] = 0;
    if (t < 64) hc[t] = 0;
    __syncthreads();

    // histogram (coalesced u16 reads, smem atomics)
#pragma unroll
    for (int i = 0; i < INPUT_DIM / EMB; i++)
        atomicAdd(&hist[g_comb[i * EMB + t] & (EMB - 1)], 1);
    __syncthreads();

    int c  = hist[t];
    int pl = (c + 3) & ~3;                 // pad to multiple of 4

    // inclusive scan of pl: warp shuffle + warp-partials
    int v = pl;
#pragma unroll
    for (int off = 1; off < 32; off <<= 1) {
        int n = __shfl_up_sync(0xffffffffu, v, off);
        if (lane >= off) v += n;
    }
    if (lane == 31) wsum[w] = v;
    __syncthreads();
    if (w == 0) {
        int s = wsum[lane];
#pragma unroll
        for (int off = 1; off < 32; off <<= 1) {
            int n = __shfl_up_sync(0xffffffffu, s, off);
            if (lane >= off) s += n;
        }
        wsum[lane] = s;
    }
    __syncthreads();
    int incl  = v + (w > 0 ? wsum[w - 1] : 0);
    int start = incl - pl;
    g_astart[t] = start;
    g_len[t]    = c;
    cur[t]      = start;

    // counting sort of buckets by length desc (key = 63 - clamp(len,63))
    int key = 63 - (c > 63 ? 63 : c);
    atomicAdd(&hc[key], 1);
    __syncthreads();
    if (w == 0) {                          // warp 0 scans 64 bins (2 per lane)
        int a = hc[lane], b2 = hc[32 + lane];
        int sa = a;
#pragma unroll
        for (int off = 1; off < 32; off <<= 1) {
            int n = __shfl_up_sync(0xffffffffu, sa, off);
            if (lane >= off) sa += n;
        }
        int tot_a = __shfl_sync(0xffffffffu, sa, 31);
        int sb = b2;
#pragma unroll
        for (int off = 1; off < 32; off <<= 1) {
            int n = __shfl_up_sync(0xffffffffu, sb, off);
            if (lane >= off) sb += n;
        }
        hoff[lane]      = sa - a;              // exclusive
        hoff[32 + lane] = tot_a + sb - b2;
    }
    __syncthreads();
    int rank = atomicAdd(&hoff[key], 1);
    g_sched[rank] = (unsigned short)t;
    __syncthreads();

    // slot assignment per feature
#pragma unroll
    for (int i = 0; i < INPUT_DIM / EMB; i++) {
        int j = i * EMB + t;
        unsigned cb = g_comb[j];
        int pos = atomicAdd(&cur[cb & (EMB - 1)], 1);
        g_pos[j] = (unsigned short)(pos | (cb & 0x8000u));
    }
}

// ---------------- K3: main kernel — scatter-on-stage, sorted balanced f4 reduce ----------------
#define GTHREADS 512
__global__ __launch_bounds__(GTHREADS, 2)
void k_gather(const float* __restrict__ x, float* __restrict__ out) {
    extern __shared__ float xs[];          // [XS_N]

    int b = blockIdx.x;
    int t = threadIdx.x;

    // Phase A: zero pad slots (<=3 per bucket)
#pragma unroll
    for (int r = 0; r < EMB / GTHREADS; r++) {
        int e  = t + r * GTHREADS;
        int s0 = __ldg(&g_astart[e]);
        int l  = __ldg(&g_len[e]);
        int pl = (l + 3) & ~3;
        for (int k = s0 + l; k < s0 + pl; k++) xs[k] = 0.0f;
    }

    // Phase B: coalesced row load + permuted, sign-applied smem scatter
    {
        const float4* gx = reinterpret_cast<const float4*>(x + (size_t)b * INPUT_DIM);
        const uint2*  gp = reinterpret_cast<const uint2*>(g_pos);
#pragma unroll
        for (int i = t; i < INPUT_DIM / 4; i += GTHREADS) {
            float4 v = gx[i];
            uint2  p = gp[i];
            unsigned p0 = p.x & 0xFFFFu, p1 = p.x >> 16;
            unsigned p2 = p.y & 0xFFFFu, p3 = p.y >> 16;
            xs[p0 & 0x7FFFu] = __uint_as_float(__float_as_uint(v.x) ^ ((p0 & 0x8000u) << 16));
            xs[p1 & 0x7FFFu] = __uint_as_float(__float_as_uint(v.y) ^ ((p1 & 0x8000u) << 16));
            xs[p2 & 0x7FFFu] = __uint_as_float(__float_as_uint(v.z) ^ ((p2 & 0x8000u) << 16));
            xs[p3 & 0x7FFFu] = __uint_as_float(__float_as_uint(v.w) ^ ((p3 & 0x8000u) << 16));
        }
    }
    __syncthreads();

    // Phase C: balanced sorted schedule, contiguous float4 reduce, direct store
    float* o = out + (size_t)b * EMB;
#pragma unroll
    for (int r = 0; r < 2; r++) {
        int idx = (r == 0) ? t : (EMB - 1 - t);   // pair longest with shortest
        int e   = __ldg(&g_sched[idx]);
        int s0  = __ldg(&g_astart[e]);
        int n4  = ((__ldg(&g_len[e]) + 3) & ~3) >> 2;
        const float4* xs4 = reinterpret_cast<const float4*>(xs) + (s0 >> 2);
        float acc = 0.0f;
        for (int i = 0; i < n4; i++) {
            float4 v = xs4[i];
            acc += (v.x + v.y) + (v.z + v.w);
        }
        o[e] = acc;
    }
}

extern "C" void kernel_launch(void* const* d_in, const int* in_sizes, int n_in,
                              void* d_out, int out_size) {
    const float* x  = (const float*)d_in[0];   // [BATCH, INPUT_DIM]
    const float* hp = (const float*)d_in[1];   // [INPUT_DIM, EMB]
    float* out = (float*)d_out;                // [BATCH, EMB]

    int smem = XS_N * (int)sizeof(float);      // 77824 B -> 2 blocks/SM
    cudaFuncSetAttribute(k_gather, cudaFuncAttributeMaxDynamicSharedMemorySize, smem);

    k_extract<<<(INPUT_DIM * 32) / 256, 256>>>(hp);
    k_build<<<1, EMB>>>();
    k_gather<<<BATCH, GTHREADS, smem>>>(x, out);
}

// round 9
// speedup vs baseline: 1.6373x; 1.6373x over previous
#include <cuda_runtime.h>
#include <cuda_bf16.h>
#include <cstdint>

#define INPUT_DIM 16384
#define EMB 1024
#define BATCH 4096
#define XS_N (INPUT_DIM + EMB * 3)   // 19456 floats, pad-4 bound (<32768, fits 15 bits)

// ---------------- device scratch ----------------
__device__ unsigned short g_comb[INPUT_DIM];                 // e | (neg<<15) per feature j
__device__ __align__(16) unsigned short g_pos[INPUT_DIM];    // slot | (neg<<15), by j
__device__ int g_astart[EMB];                                // pad-4 bucket start
__device__ int g_len[EMB];                                   // actual bucket length

// ---------------- K1: extract (bucket, sign) — batched prefetch, 2 rounds max ----------------
__global__ void k_extract(const float* __restrict__ hp) {
    int warp = (blockIdx.x * blockDim.x + threadIdx.x) >> 5;
    int lane = threadIdx.x & 31;
    if (warp >= INPUT_DIM) return;

    const float4* row = reinterpret_cast<const float4*>(hp + (size_t)warp * EMB);
    float4 c[4];
    int my_e = 0; unsigned my_neg = 0; bool has = false;

    // round 1: chunks 0-3 (cols 0..511), all 4 loads in flight
#pragma unroll
    for (int i = 0; i < 4; i++) c[i] = row[lane + i * 32];
#pragma unroll
    for (int i = 0; i < 4; i++) {
        int base = (lane + i * 32) * 4;
        if (c[i].x != 0.0f) { my_e = base + 0; my_neg = (c[i].x < 0.0f); has = true; }
        if (c[i].y != 0.0f) { my_e = base + 1; my_neg = (c[i].y < 0.0f); has = true; }
        if (c[i].z != 0.0f) { my_e = base + 2; my_neg = (c[i].z < 0.0f); has = true; }
        if (c[i].w != 0.0f) { my_e = base + 3; my_neg = (c[i].w < 0.0f); has = true; }
    }
    unsigned mask = __ballot_sync(0xffffffffu, has);

    if (mask == 0) {
        // round 2: chunks 4-7 (cols 512..1023)
#pragma unroll
        for (int i = 0; i < 4; i++) c[i] = row[lane + (i + 4) * 32];
#pragma unroll
        for (int i = 0; i < 4; i++) {
            int base = (lane + (i + 4) * 32) * 4;
            if (c[i].x != 0.0f) { my_e = base + 0; my_neg = (c[i].x < 0.0f); has = true; }
            if (c[i].y != 0.0f) { my_e = base + 1; my_neg = (c[i].y < 0.0f); has = true; }
            if (c[i].z != 0.0f) { my_e = base + 2; my_neg = (c[i].z < 0.0f); has = true; }
            if (c[i].w != 0.0f) { my_e = base + 3; my_neg = (c[i].w < 0.0f); has = true; }
        }
        mask = __ballot_sync(0xffffffffu, has);
    }

    if (mask == 0) { if (lane == 0) g_comb[warp] = 0; return; }
    int src = __ffs(mask) - 1;
    int e        = __shfl_sync(0xffffffffu, my_e, src);
    unsigned neg = __shfl_sync(0xffffffffu, my_neg, src);
    if (lane == 0) g_comb[warp] = (unsigned short)(e | (neg << 15));
}

// ---------------- K2: fused build — histogram, shuffle-scan, slot assign ----------------
__global__ __launch_bounds__(EMB, 1)
void k_build() {
    __shared__ int hist[EMB];
    __shared__ int cur[EMB];
    __shared__ int wsum[32];
    int t = threadIdx.x;
    int lane = t & 31, w = t >> 5;

    hist[t] = 0;
    __syncthreads();

    // histogram (coalesced u16 reads, smem atomics)
#pragma unroll
    for (int i = 0; i < INPUT_DIM / EMB; i++)
        atomicAdd(&hist[g_comb[i * EMB + t] & (EMB - 1)], 1);
    __syncthreads();

    int c  = hist[t];
    int pl = (c + 3) & ~3;                 // pad to multiple of 4

    // inclusive scan of pl: warp shuffle + warp-partials
    int v = pl;
#pragma unroll
    for (int off = 1; off < 32; off <<= 1) {
        int n = __shfl_up_sync(0xffffffffu, v, off);
        if (lane >= off) v += n;
    }
    if (lane == 31) wsum[w] = v;
    __syncthreads();
    if (w == 0) {
        int s = wsum[lane];
#pragma unroll
        for (int off = 1; off < 32; off <<= 1) {
            int n = __shfl_up_sync(0xffffffffu, s, off);
            if (lane >= off) s += n;
        }
        wsum[lane] = s;
    }
    __syncthreads();
    int incl  = v + (w > 0 ? wsum[w - 1] : 0);
    int start = incl - pl;
    g_astart[t] = start;
    g_len[t]    = c;
    cur[t]      = start;
    __syncthreads();

    // slot assignment per feature
#pragma unroll
    for (int i = 0; i < INPUT_DIM / EMB; i++) {
        int j = i * EMB + t;
        unsigned cb = g_comb[j];
        int pos = atomicAdd(&cur[cb & (EMB - 1)], 1);
        g_pos[j] = (unsigned short)(pos | (cb & 0x8000u));
    }
}

// ---------------- K3: main kernel — scatter-on-stage, contiguous f4 reduce (R3 form) ----------------
#define GTHREADS 512
__global__ __launch_bounds__(GTHREADS, 2)
void k_gather(const float* __restrict__ x, float* __restrict__ out) {
    extern __shared__ float xs[];          // [XS_N]

    int b = blockIdx.x;
    int t = threadIdx.x;

    // hoisted bucket metadata (overlaps Phase B latency; reused in Phases A and C)
    int s0a = __ldg(&g_astart[t]);
    int la  = __ldg(&g_len[t]);
    int s0b = __ldg(&g_astart[t + GTHREADS]);
    int lb  = __ldg(&g_len[t + GTHREADS]);

    // Phase A: zero pad slots (<=3 per bucket)
    {
        int pa = (la + 3) & ~3;
        for (int k = s0a + la; k < s0a + pa; k++) xs[k] = 0.0f;
        int pb = (lb + 3) & ~3;
        for (int k = s0b + lb; k < s0b + pb; k++) xs[k] = 0.0f;
    }

    // Phase B: coalesced row load + permuted, sign-applied smem scatter
    {
        const float4* gx = reinterpret_cast<const float4*>(x + (size_t)b * INPUT_DIM);
        const uint2*  gp = reinterpret_cast<const uint2*>(g_pos);
#pragma unroll
        for (int i = t; i < INPUT_DIM / 4; i += GTHREADS) {
            float4 v = gx[i];
            uint2  p = gp[i];
            unsigned p0 = p.x & 0xFFFFu, p1 = p.x >> 16;
            unsigned p2 = p.y & 0xFFFFu, p3 = p.y >> 16;
            xs[p0 & 0x7FFFu] = __uint_as_float(__float_as_uint(v.x) ^ ((p0 & 0x8000u) << 16));
            xs[p1 & 0x7FFFu] = __uint_as_float(__float_as_uint(v.y) ^ ((p1 & 0x8000u) << 16));
            xs[p2 & 0x7FFFu] = __uint_as_float(__float_as_uint(v.z) ^ ((p2 & 0x8000u) << 16));
            xs[p3 & 0x7FFFu] = __uint_as_float(__float_as_uint(v.w) ^ ((p3 & 0x8000u) << 16));
        }
    }
    __syncthreads();

    // Phase C: contiguous float4 streaming reduction, bucket e = t and t+512
    float* o = out + (size_t)b * EMB;
    {
        const float4* xs4 = reinterpret_cast<const float4*>(xs) + (s0a >> 2);
        int n4 = ((la + 3) & ~3) >> 2;
        float acc = 0.0f;
        for (int i = 0; i < n4; i++) {
            float4 v = xs4[i];
            acc += (v.x + v.y) + (v.z + v.w);
        }
        o[t] = acc;
    }
    {
        const float4* xs4 = reinterpret_cast<const float4*>(xs) + (s0b >> 2);
        int n4 = ((lb + 3) & ~3) >> 2;
        float acc = 0.0f;
        for (int i = 0; i < n4; i++) {
            float4 v = xs4[i];
            acc += (v.x + v.y) + (v.z + v.w);
        }
        o[t + GTHREADS] = acc;
    }
}

extern "C" void kernel_launch(void* const* d_in, const int* in_sizes, int n_in,
                              void* d_out, int out_size) {
    const float* x  = (const float*)d_in[0];   // [BATCH, INPUT_DIM]
    const float* hp = (const float*)d_in[1];   // [INPUT_DIM, EMB]
    float* out = (float*)d_out;                // [BATCH, EMB]

    int smem = XS_N * (int)sizeof(float);      // 77824 B -> 2 blocks/SM
    cudaFuncSetAttribute(k_gather, cudaFuncAttributeMaxDynamicSharedMemorySize, smem);

    k_extract<<<(INPUT_DIM * 32) / 256, 256>>>(hp);
    k_build<<<1, EMB>>>();
    k_gather<<<BATCH, GTHREADS, smem>>>(x, out);
}